// round 13
// baseline (speedup 1.0000x reference)
#include <cuda_runtime.h>
#include <cuda_bf16.h>
#include <cstdint>
#include <stdint.h>
#include <math.h>

#define Bb 16
#define Tt 1024
#define Dd 512
#define Vv 5000
#define Vp 5120
#define Lc 128
#define Mm (Bb*Tt)
#define Sz (2*Lc+1)
#define NEGV (-1e30f)
#define NLAB 129
#define JP 160              // NLAB padded for MMA tiling

// scratch (static device allocations only)
__device__ float g_lse[Mm];
__device__ float g_lab[(size_t)Bb*Tt*NLAB];
__device__ float g_loss[Bb];
__device__ __nv_bfloat16 g_Hb[(size_t)Mm*Dd];
__device__ __nv_bfloat16 g_Wb[(size_t)Dd*Vp];
__device__ __nv_bfloat16 g_Wg[(size_t)Bb*Dd*JP];   // gathered label columns (dense)
__device__ float g_bg[Bb][JP];                     // gathered bias

// ---------------------------------------------------------------------------
// helpers
// ---------------------------------------------------------------------------
__device__ __forceinline__ unsigned smaddr(const void* p)
{
    return (unsigned)__cvta_generic_to_shared(p);
}

__device__ __forceinline__ void ldsm4(unsigned* r, unsigned a)
{
    asm volatile("ldmatrix.sync.aligned.m8n8.x4.shared.b16 {%0,%1,%2,%3}, [%4];"
                 : "=r"(r[0]), "=r"(r[1]), "=r"(r[2]), "=r"(r[3])
                 : "r"(a));
}

__device__ __forceinline__ void ldsm4t(unsigned* r, unsigned a)
{
    asm volatile("ldmatrix.sync.aligned.m8n8.x4.trans.shared.b16 {%0,%1,%2,%3}, [%4];"
                 : "=r"(r[0]), "=r"(r[1]), "=r"(r[2]), "=r"(r[3])
                 : "r"(a));
}

__device__ __forceinline__ void mma16816(float* c, const unsigned* a,
                                         unsigned b0, unsigned b1)
{
    asm volatile("mma.sync.aligned.m16n8k16.row.col.f32.bf16.bf16.f32 {%0,%1,%2,%3},{%4,%5,%6,%7},{%8,%9},{%0,%1,%2,%3};"
                 : "+f"(c[0]), "+f"(c[1]), "+f"(c[2]), "+f"(c[3])
                 : "r"(a[0]), "r"(a[1]), "r"(a[2]), "r"(a[3]), "r"(b0), "r"(b1));
}

// ---------------------------------------------------------------------------
// Prep: fp32 -> bf16 conversions
// ---------------------------------------------------------------------------
__global__ void conv_h_kernel(const float* __restrict__ hs)
{
    int idx = blockIdx.x * blockDim.x + threadIdx.x;
    if (idx >= Mm * (Dd / 4)) {
        return;
    }
    int r = idx >> 7;
    int c4 = idx & 127;
    float4 v = *(const float4*)(hs + (size_t)r * Dd + c4 * 4);
    __nv_bfloat162 p0 = __floats2bfloat162_rn(v.x, v.y);
    __nv_bfloat162 p1 = __floats2bfloat162_rn(v.z, v.w);
    __nv_bfloat162* dst = (__nv_bfloat162*)(g_Hb + (size_t)r * Dd + c4 * 4);
    dst[0] = p0;
    dst[1] = p1;
}

__global__ void conv_w_kernel(const float* __restrict__ W)
{
    int idx = blockIdx.x * blockDim.x + threadIdx.x;
    if (idx >= Dd * (Vp / 4)) {
        return;
    }
    int r = idx / (Vp / 4);
    int c4 = idx % (Vp / 4);
    __nv_bfloat162 p0;
    __nv_bfloat162 p1;
    if (c4 < Vv / 4) {
        float4 v = *(const float4*)(W + (size_t)r * Vv + c4 * 4);
        p0 = __floats2bfloat162_rn(v.x, v.y);
        p1 = __floats2bfloat162_rn(v.z, v.w);
    } else {
        p0 = __floats2bfloat162_rn(0.f, 0.f);
        p1 = __floats2bfloat162_rn(0.f, 0.f);
    }
    __nv_bfloat162* dst = (__nv_bfloat162*)(g_Wb + (size_t)r * Vp + c4 * 4);
    dst[0] = p0;
    dst[1] = p1;
}

// ---------------------------------------------------------------------------
// Gather label columns of W (bf16) into dense g_Wg[b][512][JP] once.
// ---------------------------------------------------------------------------
__global__ void gather_w_kernel(const float* __restrict__ bias,
                                const int* __restrict__ ys)
{
    __shared__ int sV[JP];

    const int b   = blockIdx.y;
    const int k0  = blockIdx.x * 64;
    const int tid = threadIdx.x;

    if (tid < JP) {
        int v = -1;
        if (tid == 0) {
            v = 0;                               // blank
        } else if (tid < NLAB) {
            v = ys[b * Lc + tid - 1];
        }
        sV[tid] = v;
        if (blockIdx.x == 0) {
            g_bg[b][tid] = (v >= 0) ? bias[v] : 0.f;
        }
    }
    __syncthreads();

    for (int idx = tid; idx < 64 * JP; idx += 256) {
        int k = idx / JP;
        int j = idx % JP;
        int v = sV[j];
        __nv_bfloat16 w = __float2bfloat16(0.f);
        if (v >= 0) {
            w = g_Wb[(size_t)(k0 + k) * Vp + v];
        }
        g_Wg[((size_t)b * Dd + k0 + k) * JP + j] = w;
    }
}

// ---------------------------------------------------------------------------
// Kernel A (tensor-core): fused GEMM H x W (bf16, f32 acc) + online LSE.
// BM=64, BN=128, BK=64, 256 threads (8 warps: 2m x 4n, warp tile 32x32).
// 2 CTAs/SM; grid=256 fully co-resident.
// ---------------------------------------------------------------------------
__global__ __launch_bounds__(256, 2) void lse_mma_kernel(
    const float* __restrict__ bias)
{
    __shared__ __align__(16) __nv_bfloat16 sA[64][72];
    __shared__ __align__(16) __nv_bfloat16 sBt[64][136];
    __shared__ float sBias[128];
    __shared__ float sM[4][64];
    __shared__ float sS[4][64];

    const int mblk = blockIdx.x * 64;
    const int tid  = threadIdx.x;
    const int lane = tid & 31;
    const int wid  = tid >> 5;
    const int wm   = wid & 1;       // row warp: rows wm*32..+31
    const int wn   = wid >> 1;      // col warp: cols wn*32..+31

    float Mr[2][2];
    float Sr[2][2];
    for (int mt = 0; mt < 2; mt++) {
        for (int h = 0; h < 2; h++) {
            Mr[mt][h] = NEGV;
            Sr[mt][h] = 0.f;
        }
    }

    const int ra = tid >> 3;        // A rows ra + q*32 (q=0..1), col ca*8
    const int ca = tid & 7;
    const int rb = tid >> 4;        // B rows rb + q*16 (q=0..3), col cb*8
    const int cb = tid & 15;

    uint4 pa[2];
    uint4 pb[4];

    for (int nt = 0; nt < Vp / 128; nt++) {
        const int n0 = nt * 128;
        __syncthreads();            // previous epilogue done with smem
        if (tid < 128) {
            int n = n0 + tid;
            sBias[tid] = (n < Vv) ? bias[n] : NEGV;
        }

        float acc[2][4][4];
        for (int mt = 0; mt < 2; mt++) {
            for (int j = 0; j < 4; j++) {
                for (int e = 0; e < 4; e++) {
                    acc[mt][j][e] = 0.f;
                }
            }
        }

        // prefetch kt=0
        #pragma unroll
        for (int q = 0; q < 2; q++) {
            pa[q] = *(const uint4*)(g_Hb + (size_t)(mblk + ra + q * 32) * Dd + ca * 8);
        }
        #pragma unroll
        for (int q = 0; q < 4; q++) {
            pb[q] = *(const uint4*)(g_Wb + (size_t)(rb + q * 16) * Vp + n0 + cb * 8);
        }

        for (int kt = 0; kt < Dd / 64; kt++) {
            __syncthreads();
            #pragma unroll
            for (int q = 0; q < 2; q++) {
                *(uint4*)(&sA[ra + q * 32][ca * 8]) = pa[q];
            }
            #pragma unroll
            for (int q = 0; q < 4; q++) {
                *(uint4*)(&sBt[rb + q * 16][cb * 8]) = pb[q];
            }
            __syncthreads();
            if (kt + 1 < Dd / 64) {
                const int k0n = (kt + 1) * 64;
                #pragma unroll
                for (int q = 0; q < 2; q++) {
                    pa[q] = *(const uint4*)(g_Hb + (size_t)(mblk + ra + q * 32) * Dd + k0n + ca * 8);
                }
                #pragma unroll
                for (int q = 0; q < 4; q++) {
                    pb[q] = *(const uint4*)(g_Wb + (size_t)(k0n + rb + q * 16) * Vp + n0 + cb * 8);
                }
            }
            #pragma unroll
            for (int ks = 0; ks < 4; ks++) {
                const int k0 = ks * 16;
                unsigned afr[2][4];
                #pragma unroll
                for (int mt = 0; mt < 2; mt++) {
                    int row = wm * 32 + mt * 16 + (lane & 15);
                    int col = k0 + 8 * (lane >> 4);
                    ldsm4(afr[mt], smaddr(&sA[row][col]));
                }
                unsigned bfr[2][4];
                #pragma unroll
                for (int np = 0; np < 2; np++) {
                    int rk = k0 + (lane & 15);
                    int cn = wn * 32 + np * 16 + 8 * (lane >> 4);
                    ldsm4t(bfr[np], smaddr(&sBt[rk][cn]));
                }
                #pragma unroll
                for (int mt = 0; mt < 2; mt++) {
                    #pragma unroll
                    for (int np = 0; np < 2; np++) {
                        mma16816(acc[mt][2 * np + 0], afr[mt], bfr[np][0], bfr[np][1]);
                        mma16816(acc[mt][2 * np + 1], afr[mt], bfr[np][2], bfr[np][3]);
                    }
                }
            }
        }

        // online (max,sumexp) update for this N tile.
        // acc[mt][j] covers cols wn*32 + j*8 + (lane&3)*2, rows wm*32+mt*16+h*8+(lane>>2)
        #pragma unroll
        for (int mt = 0; mt < 2; mt++) {
            #pragma unroll
            for (int h = 0; h < 2; h++) {
                float vals[8];
                float vm = NEGV;
                #pragma unroll
                for (int j = 0; j < 4; j++) {
                    int nb = wn * 32 + j * 8 + (lane & 3) * 2;
                    float x0 = acc[mt][j][h * 2 + 0] + sBias[nb];
                    float x1 = acc[mt][j][h * 2 + 1] + sBias[nb + 1];
                    vals[j * 2 + 0] = x0;
                    vals[j * 2 + 1] = x1;
                    vm = fmaxf(vm, fmaxf(x0, x1));
                }
                float M0 = Mr[mt][h];
                float nM = fmaxf(M0, vm);
                float s  = Sr[mt][h] * __expf(M0 - nM);
                #pragma unroll
                for (int j = 0; j < 8; j++) {
                    s += __expf(vals[j] - nM);
                }
                Mr[mt][h] = nM;
                Sr[mt][h] = s;
            }
        }
    }

    // combine across the 4 lanes sharing a row, then across the 4 n-warps
    #pragma unroll
    for (int mt = 0; mt < 2; mt++) {
        #pragma unroll
        for (int h = 0; h < 2; h++) {
            float m = Mr[mt][h];
            float s = Sr[mt][h];
            #pragma unroll
            for (int off = 1; off <= 2; off <<= 1) {
                float om = __shfl_xor_sync(0xffffffffu, m, off);
                float os = __shfl_xor_sync(0xffffffffu, s, off);
                float nm = fmaxf(m, om);
                s = s * __expf(m - nm) + os * __expf(om - nm);
                m = nm;
            }
            if ((lane & 3) == 0) {
                int row = wm * 32 + mt * 16 + h * 8 + (lane >> 2);
                sM[wn][row] = m;
                sS[wn][row] = s;
            }
        }
    }
    __syncthreads();
    if (tid < 64) {
        float m = sM[0][tid];
        float s = sS[0][tid];
        #pragma unroll
        for (int w = 1; w < 4; w++) {
            float om = sM[w][tid];
            float os = sS[w][tid];
            float nm = fmaxf(m, om);
            s = s * __expf(m - nm) + os * __expf(om - nm);
            m = nm;
        }
        g_lse[mblk + tid] = m + logf(s);
    }
}

// ---------------------------------------------------------------------------
// Kernel B (tensor-core): dense label-GEMM 128x160x512 per block.
// grid (Tt/128, Bb), 256 threads (8 warps: 4m x 2n), warp tile 32x80.
// ---------------------------------------------------------------------------
__global__ __launch_bounds__(256, 1) void lab_mma_kernel()
{
    __shared__ __align__(16) __nv_bfloat16 sA[128][72];
    __shared__ __align__(16) __nv_bfloat16 sBt[64][168];
    __shared__ float sBg[JP];

    const int b    = blockIdx.y;
    const int t0   = blockIdx.x * 128;
    const int tid  = threadIdx.x;
    const int lane = tid & 31;
    const int wid  = tid >> 5;
    const int wm   = wid & 3;       // rows wm*32..+31
    const int wn   = wid >> 2;      // cols wn*80..+79

    if (tid < JP) {
        sBg[tid] = g_bg[b][tid];
    }

    const __nv_bfloat16* Aptr = g_Hb + (size_t)(b * Tt + t0) * Dd;
    const __nv_bfloat16* Bptr = g_Wg + (size_t)b * Dd * JP;

    float acc[2][10][4];
    for (int mt = 0; mt < 2; mt++) {
        for (int j = 0; j < 10; j++) {
            for (int e = 0; e < 4; e++) {
                acc[mt][j][e] = 0.f;
            }
        }
    }

    const int ra = tid >> 3;
    const int ca = tid & 7;

    uint4 pa[4];
    uint4 pb[5];

    #pragma unroll
    for (int q = 0; q < 4; q++) {
        pa[q] = *(const uint4*)(Aptr + (size_t)(ra + q * 32) * Dd + ca * 8);
    }
    #pragma unroll
    for (int q = 0; q < 5; q++) {
        int idx = q * 256 + tid;
        int r = idx / 20;
        int c = idx % 20;
        pb[q] = *(const uint4*)(Bptr + (size_t)r * JP + c * 8);
    }

    for (int kt = 0; kt < Dd / 64; kt++) {
        __syncthreads();
        #pragma unroll
        for (int q = 0; q < 4; q++) {
            *(uint4*)(&sA[ra + q * 32][ca * 8]) = pa[q];
        }
        #pragma unroll
        for (int q = 0; q < 5; q++) {
            int idx = q * 256 + tid;
            int r = idx / 20;
            int c = idx % 20;
            *(uint4*)(&sBt[r][c * 8]) = pb[q];
        }
        __syncthreads();
        if (kt + 1 < Dd / 64) {
            const int k0n = (kt + 1) * 64;
            #pragma unroll
            for (int q = 0; q < 4; q++) {
                pa[q] = *(const uint4*)(Aptr + (size_t)(ra + q * 32) * Dd + k0n + ca * 8);
            }
            #pragma unroll
            for (int q = 0; q < 5; q++) {
                int idx = q * 256 + tid;
                int r = idx / 20;
                int c = idx % 20;
                pb[q] = *(const uint4*)(Bptr + (size_t)(k0n + r) * JP + c * 8);
            }
        }
        #pragma unroll
        for (int ks = 0; ks < 4; ks++) {
            const int k0 = ks * 16;
            unsigned afr[2][4];
            #pragma unroll
            for (int mt = 0; mt < 2; mt++) {
                int row = wm * 32 + mt * 16 + (lane & 15);
                int col = k0 + 8 * (lane >> 4);
                ldsm4(afr[mt], smaddr(&sA[row][col]));
            }
            unsigned bfr[5][4];
            #pragma unroll
            for (int np = 0; np < 5; np++) {
                int rk = k0 + (lane & 15);
                int cn = wn * 80 + np * 16 + 8 * (lane >> 4);
                ldsm4t(bfr[np], smaddr(&sBt[rk][cn]));
            }
            #pragma unroll
            for (int mt = 0; mt < 2; mt++) {
                #pragma unroll
                for (int np = 0; np < 5; np++) {
                    mma16816(acc[mt][2 * np + 0], afr[mt], bfr[np][0], bfr[np][1]);
                    mma16816(acc[mt][2 * np + 1], afr[mt], bfr[np][2], bfr[np][3]);
                }
            }
        }
    }

    #pragma unroll
    for (int mt = 0; mt < 2; mt++) {
        int r0 = wm * 32 + mt * 16 + (lane >> 2);
        int r1 = r0 + 8;
        int m0 = b * Tt + t0 + r0;
        int m1 = b * Tt + t0 + r1;
        float lse0 = g_lse[m0];
        float lse1 = g_lse[m1];
        #pragma unroll
        for (int np = 0; np < 5; np++) {
            #pragma unroll
            for (int h = 0; h < 2; h++) {
                int j = wn * 80 + np * 16 + h * 8 + (lane & 3) * 2;
                float* a = acc[mt][2 * np + h];
                if (j < NLAB) {
                    g_lab[(size_t)m0 * NLAB + j] = a[0] + sBg[j] - lse0;
                    g_lab[(size_t)m1 * NLAB + j] = a[2] + sBg[j] - lse1;
                }
                if (j + 1 < NLAB) {
                    g_lab[(size_t)m0 * NLAB + j + 1] = a[1] + sBg[j + 1] - lse0;
                    g_lab[(size_t)m1 * NLAB + j + 1] = a[3] + sBg[j + 1] - lse1;
                }
            }
        }
    }
}

// ---------------------------------------------------------------------------
// Kernel C: CTC alpha recursion.
// ---------------------------------------------------------------------------
__global__ __launch_bounds__(288) void ctc_kernel(
    const int* __restrict__ hlens, const int* __restrict__ ys,
    const int* __restrict__ yslens)
{
    __shared__ float A0[Sz];
    __shared__ float A1[Sz];

    const int b   = blockIdx.x;
    const int tid = threadIdx.x;
    const int hlen = hlens[b];
    const float* lp = g_lab + (size_t)b * Tt * NLAB;

    int  labj  = 0;
    bool allow = false;
    if (tid < Sz) {
        if (tid & 1) {
            labj = (tid + 1) >> 1;
            int y     = ys[b * Lc + labj - 1];
            int yprev = (tid >= 3) ? ys[b * Lc + labj - 2] : -1;
            allow = (y != yprev);
        }
        float a0 = NEGV;
        if (tid == 0) {
            a0 = lp[0];
        }
        if (tid == 1) {
            a0 = lp[1];
        }
        A0[tid] = a0;
    }
    __syncthreads();

    float lp_cur = 0.f;
    float lp_nxt = 0.f;
    if (tid < Sz) {
        lp_cur = lp[(size_t)1 * NLAB + labj];
    }

    float* cur = A0;
    float* nxt = A1;
    for (int t = 1; t < hlen; t++) {
        if (tid < Sz) {
            int tl = (t + 1 < Tt) ? (t + 1) : (Tt - 1);
            lp_nxt = lp[(size_t)tl * NLAB + labj];
            float a1 = cur[tid];
            float a2 = (tid >= 1) ? cur[tid - 1] : NEGV;
            float a3 = (allow && tid >= 2) ? cur[tid - 2] : NEGV;
            float m  = fmaxf(fmaxf(a1, a2), a3);
            m = fmaxf(m, NEGV);
            float s = __expf(a1 - m) + __expf(a2 - m) + __expf(a3 - m);
            nxt[tid] = m + __logf(s) + lp_cur;
        }
        __syncthreads();
        lp_cur = lp_nxt;
        float* tmp = cur;
        cur = nxt;
        nxt = tmp;
    }

    if (tid == 0) {
        int yl = yslens[b];
        int i1 = 2 * yl;
        int i2 = (i1 - 1 > 0) ? (i1 - 1) : 0;
        float a = cur[i1];
        float c2 = cur[i2];
        float m = fmaxf(a, c2);
        float ll = m + __logf(__expf(a - m) + __expf(c2 - m));
        float loss = -ll;
        if (!isfinite(loss) || loss >= 1e29f) {
            loss = 0.f;
        }
        g_loss[b] = loss;
    }
}

// ---------------------------------------------------------------------------
// Kernel D: final reduction + normalization.
// ---------------------------------------------------------------------------
__global__ void final_kernel(const int* __restrict__ yslens, float* __restrict__ out)
{
    if (threadIdx.x == 0) {
        float s = 0.f;
        int tl = 0;
        for (int i = 0; i < Bb; i++) {
            s += g_loss[i];
            tl += yslens[i];
        }
        out[0] = s / (float)tl;
    }
}

extern "C" void kernel_launch(void* const* d_in, const int* in_sizes, int n_in,
                              void* d_out, int out_size)
{
    const float* hs     = (const float*)d_in[0];
    const int*   hlens  = (const int*)  d_in[1];
    const int*   ys     = (const int*)  d_in[2];
    const int*   yslens = (const int*)  d_in[3];
    const float* W      = (const float*)d_in[4];
    const float* bias   = (const float*)d_in[5];

    conv_h_kernel<<<(Mm * (Dd / 4) + 255) / 256, 256>>>(hs);
    conv_w_kernel<<<(Dd * (Vp / 4) + 255) / 256, 256>>>(W);
    dim3 gg(Dd / 64, Bb);
    gather_w_kernel<<<gg, 256>>>(bias, ys);
    lse_mma_kernel<<<Mm / 64, 256>>>(bias);
    dim3 gb(Tt / 128, Bb);
    lab_mma_kernel<<<gb, 256>>>();
    ctc_kernel<<<Bb, 288>>>(hlens, ys, yslens);
    final_kernel<<<1, 32>>>(yslens, (float*)d_out);
}